// round 13
// baseline (speedup 1.0000x reference)
#include <cuda_runtime.h>
#include <cuda_fp16.h>
#include <math.h>
#include <stdint.h>

#define E_ 8
#define D_ 1024
#define H_ 2048
#define O_ 1024
#define B_ 4096
#define S_ 8192

// ---------------- scratch (device globals) ----------------
__device__ __align__(1024) __half g_xg[S_ * D_];
__device__ __align__(1024) __half g_h1[S_ * H_];
__device__ __align__(1024) __half g_h2[S_ * H_];
__device__ __align__(1024) __half g_win[E_ * H_ * D_];   // [e][n][k]
__device__ __align__(1024) __half g_wh[E_ * H_ * H_];
__device__ __align__(1024) __half g_wo[E_ * O_ * H_];
__device__ __align__(16) float g_eo[S_ * O_];
__device__ int   g_slot[S_];
__device__ int   g_eidx[S_];
__device__ float g_wt[S_];
__device__ int   g_off[E_ + 1];
__device__ int   g_cur[E_];
__device__ int   g_done;   // zero-init; reset by last gate block each launch

struct XPtrs { const float* p[E_]; };

// ---------------- PTX wrappers (baseline-family sm_80+) ----------------
__device__ __forceinline__ uint32_t smem_u32(const void* p) {
    uint32_t a;
    asm("{ .reg .u64 t; cvta.to.shared.u64 t, %1; cvt.u32.u64 %0, t; }" : "=r"(a) : "l"(p));
    return a;
}
__device__ __forceinline__ void cp16(uint32_t dst, const void* src) {
    asm volatile("cp.async.cg.shared.global [%0], [%1], 16;" :: "r"(dst), "l"(src));
}
#define CP_COMMIT() asm volatile("cp.async.commit_group;" ::: "memory")
#define CP_WAIT2()  asm volatile("cp.async.wait_group 2;" ::: "memory")

__device__ __forceinline__ void ldsm4(uint32_t* r, uint32_t addr) {
    asm volatile("ldmatrix.sync.aligned.m8n8.x4.shared.b16 {%0,%1,%2,%3}, [%4];"
        : "=r"(r[0]), "=r"(r[1]), "=r"(r[2]), "=r"(r[3]) : "r"(addr));
}
__device__ __forceinline__ void mma16816(float* c, const uint32_t* a, const uint32_t* b) {
    asm volatile("mma.sync.aligned.m16n8k16.row.col.f32.f16.f16.f32 "
        "{%0,%1,%2,%3}, {%4,%5,%6,%7}, {%8,%9}, {%0,%1,%2,%3};"
        : "+f"(c[0]), "+f"(c[1]), "+f"(c[2]), "+f"(c[3])
        : "r"(a[0]), "r"(a[1]), "r"(a[2]), "r"(a[3]), "r"(b[0]), "r"(b[1]));
}

// ---------------- gating (with fused count/scan in last block) ----------------
__global__ void k_gate(XPtrs xs, const float* __restrict__ gw, const float* __restrict__ gb) {
    int b0 = blockIdx.x * 4;
    int tid = threadIdx.x;
    float acc[4][8];
#pragma unroll
    for (int t = 0; t < 4; t++)
#pragma unroll
        for (int e = 0; e < 8; e++) acc[t][e] = 0.f;

    const int col = tid * 4;
#pragma unroll 1
    for (int it = 0; it < E_; it++) {
        const float* xp = xs.p[it];
        const float* gwr = gw + ((long)(it * D_ + col)) * 8;
        float4 xv[4];
#pragma unroll
        for (int t = 0; t < 4; t++)
            xv[t] = *(const float4*)(xp + (long)(b0 + t) * D_ + col);
#pragma unroll
        for (int c = 0; c < 4; c++) {
            float4 w0 = *(const float4*)(gwr + c * 8);
            float4 w1 = *(const float4*)(gwr + c * 8 + 4);
#pragma unroll
            for (int t = 0; t < 4; t++) {
                float xt = ((const float*)&xv[t])[c];
                acc[t][0] = fmaf(xt, w0.x, acc[t][0]); acc[t][1] = fmaf(xt, w0.y, acc[t][1]);
                acc[t][2] = fmaf(xt, w0.z, acc[t][2]); acc[t][3] = fmaf(xt, w0.w, acc[t][3]);
                acc[t][4] = fmaf(xt, w1.x, acc[t][4]); acc[t][5] = fmaf(xt, w1.y, acc[t][5]);
                acc[t][6] = fmaf(xt, w1.z, acc[t][6]); acc[t][7] = fmaf(xt, w1.w, acc[t][7]);
            }
        }
    }
#pragma unroll
    for (int o = 16; o > 0; o >>= 1)
#pragma unroll
        for (int t = 0; t < 4; t++)
#pragma unroll
            for (int e = 0; e < 8; e++)
                acc[t][e] += __shfl_down_sync(0xffffffffu, acc[t][e], o);
    __shared__ float s[8][4][8];
    int w = tid >> 5, lane = tid & 31;
    if (lane == 0)
#pragma unroll
        for (int t = 0; t < 4; t++)
#pragma unroll
            for (int e = 0; e < 8; e++) s[w][t][e] = acc[t][e];
    __syncthreads();
    if (tid < 4) {
        int t = tid, b = b0 + t;
        float lg[8];
#pragma unroll
        for (int e = 0; e < 8; e++) {
            float a = gb[e];
#pragma unroll
            for (int w2 = 0; w2 < 8; w2++) a += s[w2][t][e];
            lg[e] = a;
        }
        int i0 = 0;
        for (int e = 1; e < 8; e++) if (lg[e] > lg[i0]) i0 = e;
        int i1 = (i0 == 0) ? 1 : 0;
        for (int e = 0; e < 8; e++) if (e != i0 && lg[e] > lg[i1]) i1 = e;
        float ex = expf(lg[i1] - lg[i0]);
        float inv = 1.f / (1.f + ex);
        g_eidx[2 * b] = i0; g_eidx[2 * b + 1] = i1;
        g_wt[2 * b] = inv;  g_wt[2 * b + 1] = ex * inv;
    }

    // ---- last block performs count + exclusive scan ----
    __shared__ int s_last;
    __syncthreads();
    if (tid == 0) {
        __threadfence();
        int d = atomicAdd(&g_done, 1);
        s_last = (d == (int)gridDim.x - 1);
    }
    __syncthreads();
    if (!s_last) return;
    __threadfence();
    __shared__ int cnts[E_];
    if (tid < E_) cnts[tid] = 0;
    __syncthreads();
    for (int i = tid; i < S_; i += 256) atomicAdd(&cnts[g_eidx[i]], 1);
    __syncthreads();
    if (tid == 0) {
        int acc2 = 0;
        for (int e = 0; e < E_; e++) { g_off[e] = acc2; g_cur[e] = acc2; acc2 += cnts[e]; }
        g_off[E_] = acc2;
        g_done = 0;
    }
}

// ---------------- fill + gather fused: one block per dispatch entry ----------------
union UH4 { __half h[4]; uint2 u; };

__global__ void k_fillgather(XPtrs xs) {
    __shared__ int s_pos, s_e, s_tok;
    int t = blockIdx.x;
    if (threadIdx.x == 0) {
        int e = g_eidx[t];
        int pos = atomicAdd(&g_cur[e], 1);
        g_slot[t] = pos;
        s_pos = pos; s_e = e; s_tok = t >> 1;
    }
    __syncthreads();
    const float4* src = (const float4*)(xs.p[s_e] + (long)s_tok * D_);
    __half* oh = g_xg + (long)s_pos * D_;
#pragma unroll
    for (int i = threadIdx.x; i < D_ / 4; i += 64) {
        float4 v = src[i];
        UH4 hv;
        hv.h[0] = __float2half_rn(v.x);
        hv.h[1] = __float2half_rn(v.y);
        hv.h[2] = __float2half_rn(v.z);
        hv.h[3] = __float2half_rn(v.w);
        *(uint2*)(oh + i * 4) = hv.u;
    }
}

// ---------------- fused weight transpose+convert: W[e][k][n] fp32 -> T[e][n][k] fp16 ----------------
// win: 16384 blocks, wh: 32768, wo: 16384 -> 65536 total (32,8) blocks
__global__ void k_convw_all(const float* __restrict__ w_in, const float* __restrict__ w_h,
                            const float* __restrict__ w_out,
                            __half* __restrict__ win, __half* __restrict__ wh,
                            __half* __restrict__ wo) {
    __shared__ float t[32][33];
    int bid = blockIdx.x;
    const float* W; __half* T; int K, N, local;
    if (bid < 16384)      { W = w_in;  T = win; K = D_; N = H_; local = bid; }
    else if (bid < 49152) { W = w_h;   T = wh;  K = H_; N = H_; local = bid - 16384; }
    else                  { W = w_out; T = wo;  K = H_; N = O_; local = bid - 49152; }
    int perE = (K >> 5) * (N >> 5);
    int e = local / perE, rem = local % perE;
    int n0 = (rem % (N >> 5)) * 32, k0 = (rem / (N >> 5)) * 32;
    long base = (long)e * K * N;
    int tx = threadIdx.x, ty = threadIdx.y;
#pragma unroll
    for (int i = 0; i < 32; i += 8)
        t[ty + i][tx] = W[base + (long)(k0 + ty + i) * N + n0 + tx];
    __syncthreads();
    long ob = (long)e * N * K;
#pragma unroll
    for (int i = 0; i < 32; i += 8)
        T[ob + (long)(n0 + ty + i) * K + k0 + tx] = __float2half_rn(t[tx][ty + i]);
}

// ---------------- HMMA GEMM (mma.sync fp16) ----------------
// BM=128, BN=256, BK=32, 256 threads (8 warps = 2m x 4n), warp tile 64x64.
// smem stage: A(10240 B) + B(20480 B) = 30720 B, pitch 40 halves. 4-stage pipeline.
#define A_B   10240
#define ST_B  30720
#define NST   4

template <int K, int N, bool RELU, bool HALF_OUT>
__global__ void __launch_bounds__(256, 1) k_mma(
    const __half* __restrict__ A, const __half* __restrict__ Bw,
    const float* __restrict__ bias,
    __half* __restrict__ oh, float* __restrict__ of) {
    const int e   = blockIdx.z;
    const int off = g_off[e];
    const int cnt = g_off[e + 1] - off;
    const int m0  = blockIdx.y * 128;
    if (m0 >= cnt) return;
    const int n0  = blockIdx.x * 256;
    const int arow0 = off + m0;

    extern __shared__ char smem[];
    __shared__ float sbias[256];
    const uint32_t sb = smem_u32(smem);

    const int tid = threadIdx.x, wid = tid >> 5, lane = tid & 31;
    sbias[tid] = bias[(long)e * N + n0 + tid];

    const int rA = tid >> 2, cq = tid & 3;
    long r0 = arow0 + rA;      if (r0 > S_ - 1) r0 = S_ - 1;
    long r1 = arow0 + rA + 64; if (r1 > S_ - 1) r1 = S_ - 1;
    const __half* a0 = A + r0 * (long)K + cq * 8;
    const __half* a1 = A + r1 * (long)K + cq * 8;
    const __half* bp = Bw + ((long)e * N + n0 + rA) * (long)K + cq * 8;
    const long bstep = 64L * K;
    const uint32_t sA = sb + rA * 80 + cq * 16;
    const uint32_t sB = sb + A_B + rA * 80 + cq * 16;

#define LOAD_STAGE(soff, koff) do {                                    \
    cp16(sA + (soff),           a0 + (koff));                          \
    cp16(sA + (soff) + 64 * 80, a1 + (koff));                          \
    _Pragma("unroll")                                                  \
    for (int j = 0; j < 4; j++)                                        \
        cp16(sB + (soff) + j * 64 * 80, bp + (koff) + j * bstep);      \
} while (0)

    LOAD_STAGE(0, 0);          CP_COMMIT();
    LOAD_STAGE(ST_B, 32);      CP_COMMIT();
    LOAD_STAGE(2 * ST_B, 64);  CP_COMMIT();

    const int base_m = (wid & 1) * 64;
    const int base_n = (wid >> 1) * 64;
    const uint32_t arow = base_m + (lane & 15);
    const uint32_t acol = (lane >> 4) << 3;
    const uint32_t brow = base_n + ((lane >> 4) << 3) + (lane & 7);
    const uint32_t bcol = ((lane >> 3) & 1) << 3;

    float acc[4][8][4];
#pragma unroll
    for (int mi = 0; mi < 4; mi++)
#pragma unroll
        for (int nj = 0; nj < 8; nj++)
#pragma unroll
            for (int q = 0; q < 4; q++) acc[mi][nj][q] = 0.f;

    const int NIT = K / 32;
#pragma unroll 1
    for (int it = 0; it < NIT; it++) {
        CP_WAIT2();
        __syncthreads();
        const uint32_t st = sb + (it & (NST - 1)) * ST_B;
#pragma unroll
        for (int ks = 0; ks < 2; ks++) {
            uint32_t a[4][4], b[4][4];
            uint32_t ab = st + (arow * 40 + ks * 16 + acol) * 2;
            uint32_t bb = st + A_B + (brow * 40 + ks * 16 + bcol) * 2;
#pragma unroll
            for (int mi = 0; mi < 4; mi++) ldsm4(a[mi], ab + mi * 1280);
#pragma unroll
            for (int ni = 0; ni < 4; ni++) ldsm4(b[ni], bb + ni * 1280);
#pragma unroll
            for (int mi = 0; mi < 4; mi++)
#pragma unroll
                for (int ni = 0; ni < 4; ni++)
#pragma unroll
                    for (int h = 0; h < 2; h++)
                        mma16816(acc[mi][ni * 2 + h], a[mi], &b[ni][h * 2]);
        }
        if (it + 3 < NIT) {
            const uint32_t so = ((it + 3) & (NST - 1)) * ST_B;
            LOAD_STAGE(so, (it + 3) * 32);
        }
        CP_COMMIT();
    }
#undef LOAD_STAGE

#pragma unroll
    for (int mi = 0; mi < 4; mi++) {
        int gr0 = m0 + base_m + mi * 16 + (lane >> 2);
        bool v0 = gr0 < cnt, v1 = (gr0 + 8) < cnt;
        long s0 = (long)(off + gr0), s1 = s0 + 8;
#pragma unroll
        for (int nj = 0; nj < 8; nj++) {
            int col = base_n + nj * 8 + (lane & 3) * 2;
            float2 bv = *(float2*)&sbias[col];
            float x0 = acc[mi][nj][0] + bv.x;
            float x1 = acc[mi][nj][1] + bv.y;
            float x2 = acc[mi][nj][2] + bv.x;
            float x3 = acc[mi][nj][3] + bv.y;
            if (RELU) {
                x0 = fmaxf(x0, 0.f); x1 = fmaxf(x1, 0.f);
                x2 = fmaxf(x2, 0.f); x3 = fmaxf(x3, 0.f);
            }
            long gcol = n0 + col;
            if (HALF_OUT) {
                if (v0) {
                    __half2 hp; hp.x = __float2half_rn(x0); hp.y = __float2half_rn(x1);
                    *(__half2*)(oh + s0 * N + gcol) = hp;
                }
                if (v1) {
                    __half2 hp; hp.x = __float2half_rn(x2); hp.y = __float2half_rn(x3);
                    *(__half2*)(oh + s1 * N + gcol) = hp;
                }
            } else {
                if (v0) { float2 v; v.x = x0; v.y = x1; *(float2*)(of + s0 * N + gcol) = v; }
                if (v1) { float2 v; v.x = x2; v.y = x3; *(float2*)(of + s1 * N + gcol) = v; }
            }
        }
    }
}

// ---------------- combine ----------------
__global__ void k_combine(float* __restrict__ out) {
    int idx = blockIdx.x * 256 + threadIdx.x;
    int b = idx >> 8;
    int o4 = idx & 255;
    float w0 = g_wt[2 * b], w1 = g_wt[2 * b + 1];
    const float4* r0 = (const float4*)(g_eo + (long)g_slot[2 * b] * O_);
    const float4* r1 = (const float4*)(g_eo + (long)g_slot[2 * b + 1] * O_);
    float4 a = r0[o4], c = r1[o4], v;
    v.x = w0 * a.x + w1 * c.x;
    v.y = w0 * a.y + w1 * c.y;
    v.z = w0 * a.z + w1 * c.z;
    v.w = w0 * a.w + w1 * c.w;
    ((float4*)out)[idx] = v;
}

// ---------------- host ----------------
#define SMEM_DYN (NST * ST_B)

extern "C" void kernel_launch(void* const* d_in, const int* in_sizes, int n_in,
                              void* d_out, int out_size) {
    XPtrs xs;
    for (int i = 0; i < E_; i++) xs.p[i] = (const float*)d_in[i];
    const float* gw    = (const float*)d_in[8];
    const float* gb    = (const float*)d_in[9];
    const float* w_in  = (const float*)d_in[10];
    const float* b_in  = (const float*)d_in[11];
    const float* w_h   = (const float*)d_in[12];
    const float* b_h   = (const float*)d_in[13];
    const float* w_out = (const float*)d_in[14];
    const float* b_out = (const float*)d_in[15];
    float* out = (float*)d_out;

    void *xg, *h1, *h2, *win, *wh, *wo, *eo;
    cudaGetSymbolAddress(&xg, g_xg);
    cudaGetSymbolAddress(&h1, g_h1);
    cudaGetSymbolAddress(&h2, g_h2);
    cudaGetSymbolAddress(&win, g_win);
    cudaGetSymbolAddress(&wh, g_wh);
    cudaGetSymbolAddress(&wo, g_wo);
    cudaGetSymbolAddress(&eo, g_eo);

    cudaFuncSetAttribute((const void*)k_mma<1024, 2048, true, true>,
                         cudaFuncAttributeMaxDynamicSharedMemorySize, SMEM_DYN);
    cudaFuncSetAttribute((const void*)k_mma<2048, 2048, true, true>,
                         cudaFuncAttributeMaxDynamicSharedMemorySize, SMEM_DYN);
    cudaFuncSetAttribute((const void*)k_mma<2048, 1024, false, false>,
                         cudaFuncAttributeMaxDynamicSharedMemorySize, SMEM_DYN);

    k_gate<<<B_ / 4, 256>>>(xs, gw, gb);                 // launch 0 (scan fused)
    k_fillgather<<<S_, 64>>>(xs);                        // launch 1
    k_convw_all<<<65536, dim3(32, 8)>>>(w_in, w_h, w_out,
        (__half*)win, (__half*)wh, (__half*)wo);         // launch 2
    k_mma<1024, 2048, true, true><<<dim3(H_ / 256, S_ / 128, E_), 256, SMEM_DYN>>>(
        (const __half*)xg, (const __half*)win, b_in, (__half*)h1, nullptr);   // launch 3 (profiled)
    k_mma<2048, 2048, true, true><<<dim3(H_ / 256, S_ / 128, E_), 256, SMEM_DYN>>>(
        (const __half*)h1, (const __half*)wh, b_h, (__half*)h2, nullptr);
    k_mma<2048, 1024, false, false><<<dim3(O_ / 256, S_ / 128, E_), 256, SMEM_DYN>>>(
        (const __half*)h2, (const __half*)wo, b_out, nullptr, (float*)eo);
    k_combine<<<(B_ * O_ / 4) / 256, 256>>>(out);
}

// round 15
// speedup vs baseline: 1.1196x; 1.1196x over previous
#include <cuda_runtime.h>
#include <cuda_fp16.h>
#include <math.h>
#include <stdint.h>

#define E_ 8
#define D_ 1024
#define H_ 2048
#define O_ 1024
#define B_ 4096
#define S_ 8192

// ---------------- scratch (device globals) ----------------
__device__ __align__(1024) __half g_xg[S_ * D_];
__device__ __align__(1024) __half g_h1[S_ * H_];
__device__ __align__(1024) __half g_h2[S_ * H_];
__device__ __align__(1024) __half g_win[E_ * H_ * D_];   // [e][n][k]
__device__ __align__(1024) __half g_wh[E_ * H_ * H_];
__device__ __align__(1024) __half g_wo[E_ * O_ * H_];
__device__ __align__(16) float g_eo[S_ * O_];
__device__ int   g_rows[S_];
__device__ int   g_sexp[S_];
__device__ int   g_slot[S_];
__device__ int   g_eidx[S_];
__device__ float g_wt[S_];
__device__ int   g_cnt[E_];
__device__ int   g_off[E_ + 1];
__device__ int   g_cur[E_];

struct XPtrs { const float* p[E_]; };

// ---------------- PTX wrappers (baseline-family sm_80+) ----------------
__device__ __forceinline__ uint32_t smem_u32(const void* p) {
    uint32_t a;
    asm("{ .reg .u64 t; cvta.to.shared.u64 t, %1; cvt.u32.u64 %0, t; }" : "=r"(a) : "l"(p));
    return a;
}
__device__ __forceinline__ void cp16(uint32_t dst, const void* src) {
    asm volatile("cp.async.cg.shared.global [%0], [%1], 16;" :: "r"(dst), "l"(src));
}
#define CP_COMMIT() asm volatile("cp.async.commit_group;" ::: "memory")
#define CP_WAIT2()  asm volatile("cp.async.wait_group 2;" ::: "memory")

__device__ __forceinline__ void ldsm4(uint32_t* r, uint32_t addr) {
    asm volatile("ldmatrix.sync.aligned.m8n8.x4.shared.b16 {%0,%1,%2,%3}, [%4];"
        : "=r"(r[0]), "=r"(r[1]), "=r"(r[2]), "=r"(r[3]) : "r"(addr));
}
__device__ __forceinline__ void mma16816(float* c, const uint32_t* a, const uint32_t* b) {
    asm volatile("mma.sync.aligned.m16n8k16.row.col.f32.f16.f16.f32 "
        "{%0,%1,%2,%3}, {%4,%5,%6,%7}, {%8,%9}, {%0,%1,%2,%3};"
        : "+f"(c[0]), "+f"(c[1]), "+f"(c[2]), "+f"(c[3])
        : "r"(a[0]), "r"(a[1]), "r"(a[2]), "r"(a[3]), "r"(b[0]), "r"(b[1]));
}

// ---------------- gating / dispatch (round-11 versions — measured fastest) ----------------
__global__ void k_zero() { if (threadIdx.x < E_) g_cnt[threadIdx.x] = 0; }

__global__ void k_gate(XPtrs xs, const float* __restrict__ gw, const float* __restrict__ gb) {
    int b0 = blockIdx.x * 4;
    int tid = threadIdx.x;
    float acc[4][8];
#pragma unroll
    for (int t = 0; t < 4; t++)
#pragma unroll
        for (int e = 0; e < 8; e++) acc[t][e] = 0.f;
    for (int j = tid; j < E_ * D_; j += 256) {
        const float* xp = xs.p[j >> 10];
        int col = j & (D_ - 1);
        float4 w0 = *(const float4*)(gw + (long)j * 8);
        float4 w1 = *(const float4*)(gw + (long)j * 8 + 4);
#pragma unroll
        for (int t = 0; t < 4; t++) {
            float v = xp[(long)(b0 + t) * D_ + col];
            acc[t][0] = fmaf(v, w0.x, acc[t][0]); acc[t][1] = fmaf(v, w0.y, acc[t][1]);
            acc[t][2] = fmaf(v, w0.z, acc[t][2]); acc[t][3] = fmaf(v, w0.w, acc[t][3]);
            acc[t][4] = fmaf(v, w1.x, acc[t][4]); acc[t][5] = fmaf(v, w1.y, acc[t][5]);
            acc[t][6] = fmaf(v, w1.z, acc[t][6]); acc[t][7] = fmaf(v, w1.w, acc[t][7]);
        }
    }
#pragma unroll
    for (int o = 16; o > 0; o >>= 1)
#pragma unroll
        for (int t = 0; t < 4; t++)
#pragma unroll
            for (int e = 0; e < 8; e++)
                acc[t][e] += __shfl_down_sync(0xffffffffu, acc[t][e], o);
    __shared__ float s[8][4][8];
    int w = tid >> 5, lane = tid & 31;
    if (lane == 0)
#pragma unroll
        for (int t = 0; t < 4; t++)
#pragma unroll
            for (int e = 0; e < 8; e++) s[w][t][e] = acc[t][e];
    __syncthreads();
    if (tid < 4) {
        int t = tid, b = b0 + t;
        float lg[8];
#pragma unroll
        for (int e = 0; e < 8; e++) {
            float a = gb[e];
#pragma unroll
            for (int w2 = 0; w2 < 8; w2++) a += s[w2][t][e];
            lg[e] = a;
        }
        int i0 = 0;
        for (int e = 1; e < 8; e++) if (lg[e] > lg[i0]) i0 = e;
        int i1 = (i0 == 0) ? 1 : 0;
        for (int e = 0; e < 8; e++) if (e != i0 && lg[e] > lg[i1]) i1 = e;
        float ex = expf(lg[i1] - lg[i0]);
        float inv = 1.f / (1.f + ex);
        g_eidx[2 * b] = i0; g_eidx[2 * b + 1] = i1;
        g_wt[2 * b] = inv;  g_wt[2 * b + 1] = ex * inv;
        atomicAdd(&g_cnt[i0], 1);
        atomicAdd(&g_cnt[i1], 1);
    }
}

__global__ void k_scan() {
    if (threadIdx.x == 0) {
        int acc = 0;
        for (int e = 0; e < E_; e++) { g_off[e] = acc; g_cur[e] = acc; acc += g_cnt[e]; }
        g_off[E_] = acc;
    }
}

__global__ void k_fill() {
    int t = blockIdx.x * blockDim.x + threadIdx.x;
    if (t < S_) {
        int e = g_eidx[t];
        int pos = atomicAdd(&g_cur[e], 1);
        g_rows[pos] = t >> 1;
        g_sexp[pos] = e;
        g_slot[t] = pos;
    }
}

union UH4 { __half h[4]; uint2 u; };

__global__ void k_gather(XPtrs xs) {
    int sIdx = blockIdx.x;
    int e = g_sexp[sIdx];
    long t = g_rows[sIdx];
    const float4* src = (const float4*)(xs.p[e] + t * D_);
    __half* oh = g_xg + (long)sIdx * D_;
    for (int i = threadIdx.x; i < D_ / 4; i += 128) {
        float4 v = src[i];
        UH4 hv;
        hv.h[0] = __float2half_rn(v.x);
        hv.h[1] = __float2half_rn(v.y);
        hv.h[2] = __float2half_rn(v.z);
        hv.h[3] = __float2half_rn(v.w);
        *(uint2*)(oh + i * 4) = hv.u;
    }
}

// transpose: W[e][k][n] fp32 -> Wt[e][n][k] fp16
__global__ void k_convw(const float* __restrict__ W, __half* __restrict__ T, int K, int N) {
    __shared__ float t[32][33];
    int e = blockIdx.z;
    long base = (long)e * K * N;
    int n0 = blockIdx.x * 32, k0 = blockIdx.y * 32;
    int tx = threadIdx.x, ty = threadIdx.y;
#pragma unroll
    for (int i = 0; i < 32; i += 8)
        t[ty + i][tx] = W[base + (long)(k0 + ty + i) * N + n0 + tx];
    __syncthreads();
    long ob = (long)e * N * K;
#pragma unroll
    for (int i = 0; i < 32; i += 8)
        T[ob + (long)(n0 + ty + i) * K + k0 + tx] = __float2half_rn(t[tx][ty + i]);
}

// ---------------- HMMA GEMM (mma.sync fp16) ----------------
// BM=128, BN=128, BK=32, 128 threads (4 warps = 2m x 2n), warp tile 64x64.
// 2 CTAs per SM (register-fit: 128thr x ~200regs x 2 = 51K < 64K).
// smem stage: A(10240 B) + B(10240 B) = 20480 B, pitch 40 halves. 4-stage pipeline.
#define A_B   10240
#define ST_B  20480
#define NST   4

template <int K, int N, bool RELU, bool HALF_OUT>
__global__ void __launch_bounds__(128, 2) k_mma(
    const __half* __restrict__ A, const __half* __restrict__ Bw,
    const float* __restrict__ bias,
    __half* __restrict__ oh, float* __restrict__ of) {
    const int e   = blockIdx.z;
    const int off = g_off[e];
    const int cnt = g_off[e + 1] - off;
    const int m0  = blockIdx.y * 128;
    if (m0 >= cnt) return;
    const int n0  = blockIdx.x * 128;
    const int arow0 = off + m0;

    extern __shared__ char smem[];
    __shared__ float sbias[128];
    const uint32_t sb = smem_u32(smem);

    const int tid = threadIdx.x, wid = tid >> 5, lane = tid & 31;
    sbias[tid] = bias[(long)e * N + n0 + tid];

    // ---- load plan: rA = tid>>2 (0..31), cq = tid&3; rows rA+{0,32,64,96} for A and B ----
    const int rA = tid >> 2, cq = tid & 3;
    const __half* ap[4];
    const __half* bp[4];
#pragma unroll
    for (int j = 0; j < 4; j++) {
        long r = arow0 + rA + 32 * j;
        if (r > S_ - 1) r = S_ - 1;
        ap[j] = A + r * (long)K + cq * 8;
        bp[j] = Bw + ((long)e * N + n0 + rA + 32 * j) * (long)K + cq * 8;
    }
    const uint32_t sA = sb + rA * 80 + cq * 16;
    const uint32_t sB = sb + A_B + rA * 80 + cq * 16;

#define LOAD_STAGE(soff, koff) do {                                    \
    _Pragma("unroll")                                                  \
    for (int j = 0; j < 4; j++) {                                      \
        cp16(sA + (soff) + j * 32 * 80, ap[j] + (koff));               \
        cp16(sB + (soff) + j * 32 * 80, bp[j] + (koff));               \
    }                                                                  \
} while (0)

    LOAD_STAGE(0, 0);          CP_COMMIT();
    LOAD_STAGE(ST_B, 32);      CP_COMMIT();
    LOAD_STAGE(2 * ST_B, 64);  CP_COMMIT();

    // ---- warp tiling: 2m x 2n, warp tile 64x64 ----
    const int base_m = (wid & 1) * 64;
    const int base_n = (wid >> 1) * 64;
    const uint32_t arow = base_m + (lane & 15);
    const uint32_t acol = (lane >> 4) << 3;
    const uint32_t brow = base_n + ((lane >> 4) << 3) + (lane & 7);
    const uint32_t bcol = ((lane >> 3) & 1) << 3;

    float acc[4][8][4];
#pragma unroll
    for (int mi = 0; mi < 4; mi++)
#pragma unroll
        for (int nj = 0; nj < 8; nj++)
#pragma unroll
            for (int q = 0; q < 4; q++) acc[mi][nj][q] = 0.f;

    const int NIT = K / 32;
#pragma unroll 1
    for (int it = 0; it < NIT; it++) {
        CP_WAIT2();
        __syncthreads();
        const uint32_t st = sb + (it & (NST - 1)) * ST_B;
#pragma unroll
        for (int ks = 0; ks < 2; ks++) {
            uint32_t a[4][4], b[4][4];
            uint32_t ab = st + (arow * 40 + ks * 16 + acol) * 2;
            uint32_t bb = st + A_B + (brow * 40 + ks * 16 + bcol) * 2;
#pragma unroll
            for (int mi = 0; mi < 4; mi++) ldsm4(a[mi], ab + mi * 1280);
#pragma unroll
            for (int ni = 0; ni < 4; ni++) ldsm4(b[ni], bb + ni * 1280);
#pragma unroll
            for (int mi = 0; mi < 4; mi++)
#pragma unroll
                for (int ni = 0; ni < 4; ni++)
#pragma unroll
                    for (int h = 0; h < 2; h++)
                        mma16816(acc[mi][ni * 2 + h], a[mi], &b[ni][h * 2]);
        }
        if (it + 3 < NIT) {
            const uint32_t so = ((it + 3) & (NST - 1)) * ST_B;
            LOAD_STAGE(so, (it + 3) * 32);
        }
        CP_COMMIT();
    }
#undef LOAD_STAGE

    // ---- epilogue ----
#pragma unroll
    for (int mi = 0; mi < 4; mi++) {
        int gr0 = m0 + base_m + mi * 16 + (lane >> 2);
        bool v0 = gr0 < cnt, v1 = (gr0 + 8) < cnt;
        long s0 = (long)(off + gr0), s1 = s0 + 8;
#pragma unroll
        for (int nj = 0; nj < 8; nj++) {
            int col = base_n + nj * 8 + (lane & 3) * 2;
            float2 bv = *(float2*)&sbias[col];
            float x0 = acc[mi][nj][0] + bv.x;
            float x1 = acc[mi][nj][1] + bv.y;
            float x2 = acc[mi][nj][2] + bv.x;
            float x3 = acc[mi][nj][3] + bv.y;
            if (RELU) {
                x0 = fmaxf(x0, 0.f); x1 = fmaxf(x1, 0.f);
                x2 = fmaxf(x2, 0.f); x3 = fmaxf(x3, 0.f);
            }
            long gcol = n0 + col;
            if (HALF_OUT) {
                if (v0) {
                    __half2 hp; hp.x = __float2half_rn(x0); hp.y = __float2half_rn(x1);
                    *(__half2*)(oh + s0 * N + gcol) = hp;
                }
                if (v1) {
                    __half2 hp; hp.x = __float2half_rn(x2); hp.y = __float2half_rn(x3);
                    *(__half2*)(oh + s1 * N + gcol) = hp;
                }
            } else {
                if (v0) { float2 v; v.x = x0; v.y = x1; *(float2*)(of + s0 * N + gcol) = v; }
                if (v1) { float2 v; v.x = x2; v.y = x3; *(float2*)(of + s1 * N + gcol) = v; }
            }
        }
    }
}

// ---------------- combine ----------------
__global__ void k_combine(float* __restrict__ out) {
    int idx = blockIdx.x * 256 + threadIdx.x;
    int b = idx >> 8;
    int o4 = idx & 255;
    float w0 = g_wt[2 * b], w1 = g_wt[2 * b + 1];
    const float4* r0 = (const float4*)(g_eo + (long)g_slot[2 * b] * O_);
    const float4* r1 = (const float4*)(g_eo + (long)g_slot[2 * b + 1] * O_);
    float4 a = r0[o4], c = r1[o4], v;
    v.x = w0 * a.x + w1 * c.x;
    v.y = w0 * a.y + w1 * c.y;
    v.z = w0 * a.z + w1 * c.z;
    v.w = w0 * a.w + w1 * c.w;
    ((float4*)out)[idx] = v;
}

// ---------------- host ----------------
#define SMEM_DYN (NST * ST_B)

extern "C" void kernel_launch(void* const* d_in, const int* in_sizes, int n_in,
                              void* d_out, int out_size) {
    XPtrs xs;
    for (int i = 0; i < E_; i++) xs.p[i] = (const float*)d_in[i];
    const float* gw    = (const float*)d_in[8];
    const float* gb    = (const float*)d_in[9];
    const float* w_in  = (const float*)d_in[10];
    const float* b_in  = (const float*)d_in[11];
    const float* w_h   = (const float*)d_in[12];
    const float* b_h   = (const float*)d_in[13];
    const float* w_out = (const float*)d_in[14];
    const float* b_out = (const float*)d_in[15];
    float* out = (float*)d_out;

    void *xg, *h1, *h2, *win, *wh, *wo, *eo;
    cudaGetSymbolAddress(&xg, g_xg);
    cudaGetSymbolAddress(&h1, g_h1);
    cudaGetSymbolAddress(&h2, g_h2);
    cudaGetSymbolAddress(&win, g_win);
    cudaGetSymbolAddress(&wh, g_wh);
    cudaGetSymbolAddress(&wo, g_wo);
    cudaGetSymbolAddress(&eo, g_eo);

    cudaFuncSetAttribute((const void*)k_mma<1024, 2048, true, true>,
                         cudaFuncAttributeMaxDynamicSharedMemorySize, SMEM_DYN);
    cudaFuncSetAttribute((const void*)k_mma<2048, 2048, true, true>,
                         cudaFuncAttributeMaxDynamicSharedMemorySize, SMEM_DYN);
    cudaFuncSetAttribute((const void*)k_mma<2048, 1024, false, false>,
                         cudaFuncAttributeMaxDynamicSharedMemorySize, SMEM_DYN);

    k_zero<<<1, 32>>>();
    k_gate<<<B_ / 4, 256>>>(xs, gw, gb);
    k_scan<<<1, 32>>>();
    k_fill<<<S_ / 256, 256>>>();                         // launch 3
    k_gather<<<S_, 128>>>(xs);
    k_convw<<<dim3(H_ / 32, D_ / 32, E_), dim3(32, 8)>>>(w_in, (__half*)win, D_, H_);
    k_convw<<<dim3(H_ / 32, H_ / 32, E_), dim3(32, 8)>>>(w_h, (__half*)wh, H_, H_);
    k_convw<<<dim3(O_ / 32, H_ / 32, E_), dim3(32, 8)>>>(w_out, (__half*)wo, H_, O_);

    k_mma<1024, 2048, true, true><<<dim3(H_ / 128, S_ / 128, E_), 128, SMEM_DYN>>>(
        (const __half*)xg, (const __half*)win, b_in, (__half*)h1, nullptr);
    k_mma<2048, 2048, true, true><<<dim3(H_ / 128, S_ / 128, E_), 128, SMEM_DYN>>>(
        (const __half*)h1, (const __half*)wh, b_h, (__half*)h2, nullptr);
    k_mma<2048, 1024, false, false><<<dim3(O_ / 128, S_ / 128, E_), 128, SMEM_DYN>>>(
        (const __half*)h2, (const __half*)wo, b_out, nullptr, (float*)eo);

    k_combine<<<(B_ * O_ / 4) / 256, 256>>>(out);
}

// round 16
// speedup vs baseline: 1.1239x; 1.0038x over previous
#include <cuda_runtime.h>
#include <cuda_fp16.h>
#include <math.h>
#include <stdint.h>

#define E_ 8
#define D_ 1024
#define H_ 2048
#define O_ 1024
#define B_ 4096
#define S_ 8192

// ---------------- scratch (device globals) ----------------
__device__ __align__(1024) __half g_xg[S_ * D_];
__device__ __align__(1024) __half g_h1[S_ * H_];
__device__ __align__(1024) __half g_h2[S_ * H_];
__device__ __align__(1024) __half g_win[E_ * H_ * D_];   // [e][n][k]
__device__ __align__(1024) __half g_wh[E_ * H_ * H_];
__device__ __align__(1024) __half g_wo[E_ * O_ * H_];
__device__ __align__(16) float g_eo[S_ * O_];
__device__ int   g_rows[S_];
__device__ int   g_sexp[S_];
__device__ int   g_slot[S_];
__device__ int   g_eidx[S_];
__device__ float g_wt[S_];
__device__ int   g_cnt[E_];
__device__ int   g_off[E_ + 1];
__device__ int   g_cur[E_];

struct XPtrs { const float* p[E_]; };

// ---------------- PTX wrappers (baseline-family sm_80+) ----------------
__device__ __forceinline__ uint32_t smem_u32(const void* p) {
    uint32_t a;
    asm("{ .reg .u64 t; cvta.to.shared.u64 t, %1; cvt.u32.u64 %0, t; }" : "=r"(a) : "l"(p));
    return a;
}
__device__ __forceinline__ void cp16(uint32_t dst, const void* src) {
    asm volatile("cp.async.cg.shared.global [%0], [%1], 16;" :: "r"(dst), "l"(src));
}
#define CP_COMMIT() asm volatile("cp.async.commit_group;" ::: "memory")
#define CP_WAIT2()  asm volatile("cp.async.wait_group 2;" ::: "memory")

__device__ __forceinline__ void ldsm4(uint32_t* r, uint32_t addr) {
    asm volatile("ldmatrix.sync.aligned.m8n8.x4.shared.b16 {%0,%1,%2,%3}, [%4];"
        : "=r"(r[0]), "=r"(r[1]), "=r"(r[2]), "=r"(r[3]) : "r"(addr));
}
__device__ __forceinline__ void mma16816(float* c, const uint32_t* a, const uint32_t* b) {
    asm volatile("mma.sync.aligned.m16n8k16.row.col.f32.f16.f16.f32 "
        "{%0,%1,%2,%3}, {%4,%5,%6,%7}, {%8,%9}, {%0,%1,%2,%3};"
        : "+f"(c[0]), "+f"(c[1]), "+f"(c[2]), "+f"(c[3])
        : "r"(a[0]), "r"(a[1]), "r"(a[2]), "r"(a[3]), "r"(b[0]), "r"(b[1]));
}

// ---------------- gating / dispatch ----------------
__global__ void k_zero() { if (threadIdx.x < E_) g_cnt[threadIdx.x] = 0; }

__global__ void k_gate(XPtrs xs, const float* __restrict__ gw, const float* __restrict__ gb) {
    int b0 = blockIdx.x * 4;
    int tid = threadIdx.x;
    float acc[4][8];
#pragma unroll
    for (int t = 0; t < 4; t++)
#pragma unroll
        for (int e = 0; e < 8; e++) acc[t][e] = 0.f;
    for (int j = tid; j < E_ * D_; j += 256) {
        const float* xp = xs.p[j >> 10];
        int col = j & (D_ - 1);
        float4 w0 = *(const float4*)(gw + (long)j * 8);
        float4 w1 = *(const float4*)(gw + (long)j * 8 + 4);
#pragma unroll
        for (int t = 0; t < 4; t++) {
            float v = xp[(long)(b0 + t) * D_ + col];
            acc[t][0] = fmaf(v, w0.x, acc[t][0]); acc[t][1] = fmaf(v, w0.y, acc[t][1]);
            acc[t][2] = fmaf(v, w0.z, acc[t][2]); acc[t][3] = fmaf(v, w0.w, acc[t][3]);
            acc[t][4] = fmaf(v, w1.x, acc[t][4]); acc[t][5] = fmaf(v, w1.y, acc[t][5]);
            acc[t][6] = fmaf(v, w1.z, acc[t][6]); acc[t][7] = fmaf(v, w1.w, acc[t][7]);
        }
    }
#pragma unroll
    for (int o = 16; o > 0; o >>= 1)
#pragma unroll
        for (int t = 0; t < 4; t++)
#pragma unroll
            for (int e = 0; e < 8; e++)
                acc[t][e] += __shfl_down_sync(0xffffffffu, acc[t][e], o);
    __shared__ float s[8][4][8];
    int w = tid >> 5, lane = tid & 31;
    if (lane == 0)
#pragma unroll
        for (int t = 0; t < 4; t++)
#pragma unroll
            for (int e = 0; e < 8; e++) s[w][t][e] = acc[t][e];
    __syncthreads();
    if (tid < 4) {
        int t = tid, b = b0 + t;
        float lg[8];
#pragma unroll
        for (int e = 0; e < 8; e++) {
            float a = gb[e];
#pragma unroll
            for (int w2 = 0; w2 < 8; w2++) a += s[w2][t][e];
            lg[e] = a;
        }
        int i0 = 0;
        for (int e = 1; e < 8; e++) if (lg[e] > lg[i0]) i0 = e;
        int i1 = (i0 == 0) ? 1 : 0;
        for (int e = 0; e < 8; e++) if (e != i0 && lg[e] > lg[i1]) i1 = e;
        float ex = expf(lg[i1] - lg[i0]);
        float inv = 1.f / (1.f + ex);
        g_eidx[2 * b] = i0; g_eidx[2 * b + 1] = i1;
        g_wt[2 * b] = inv;  g_wt[2 * b + 1] = ex * inv;
        atomicAdd(&g_cnt[i0], 1);
        atomicAdd(&g_cnt[i1], 1);
    }
}

__global__ void k_scan() {
    if (threadIdx.x == 0) {
        int acc = 0;
        for (int e = 0; e < E_; e++) { g_off[e] = acc; g_cur[e] = acc; acc += g_cnt[e]; }
        g_off[E_] = acc;
    }
}

__global__ void k_fill() {
    int t = blockIdx.x * blockDim.x + threadIdx.x;
    if (t < S_) {
        int e = g_eidx[t];
        int pos = atomicAdd(&g_cur[e], 1);
        g_rows[pos] = t >> 1;
        g_sexp[pos] = e;
        g_slot[t] = pos;
    }
}

union UH4 { __half h[4]; uint2 u; };

__global__ void k_gather(XPtrs xs) {
    int sIdx = blockIdx.x;
    int e = g_sexp[sIdx];
    long t = g_rows[sIdx];
    const float4* src = (const float4*)(xs.p[e] + t * D_);
    __half* oh = g_xg + (long)sIdx * D_;
    for (int i = threadIdx.x; i < D_ / 4; i += 128) {
        float4 v = src[i];
        UH4 hv;
        hv.h[0] = __float2half_rn(v.x);
        hv.h[1] = __float2half_rn(v.y);
        hv.h[2] = __float2half_rn(v.z);
        hv.h[3] = __float2half_rn(v.w);
        *(uint2*)(oh + i * 4) = hv.u;
    }
}

// transpose: W[e][k][n] fp32 -> Wt[e][n][k] fp16
__global__ void k_convw(const float* __restrict__ W, __half* __restrict__ T, int K, int N) {
    __shared__ float t[32][33];
    int e = blockIdx.z;
    long base = (long)e * K * N;
    int n0 = blockIdx.x * 32, k0 = blockIdx.y * 32;
    int tx = threadIdx.x, ty = threadIdx.y;
#pragma unroll
    for (int i = 0; i < 32; i += 8)
        t[ty + i][tx] = W[base + (long)(k0 + ty + i) * N + n0 + tx];
    __syncthreads();
    long ob = (long)e * N * K;
#pragma unroll
    for (int i = 0; i < 32; i += 8)
        T[ob + (long)(n0 + ty + i) * K + k0 + tx] = __float2half_rn(t[tx][ty + i]);
}

// ---------------- HMMA GEMM (mma.sync fp16) ----------------
// BM=128, BN=128, BK=32, 128 threads (4 warps = 2m x 2n), warp tile 64x64.
// 2 CTAs per SM. smem stage: A(10240) + B(10240) = 20480 B. 4-stage pipeline.
#define A_B   10240
#define ST_B  20480
#define NST   4

template <int K, int N, bool RELU, bool HALF_OUT>
__global__ void __launch_bounds__(128, 2) k_mma(
    const __half* __restrict__ A, const __half* __restrict__ Bw,
    const float* __restrict__ bias,
    __half* __restrict__ oh, float* __restrict__ of) {
    const int e   = blockIdx.z;
    const int off = g_off[e];
    const int cnt = g_off[e + 1] - off;
    const int m0  = blockIdx.y * 128;
    if (m0 >= cnt) return;
    const int n0  = blockIdx.x * 128;
    const int arow0 = off + m0;

    extern __shared__ char smem[];
    __shared__ float sbias[128];
    const uint32_t sb = smem_u32(smem);

    const int tid = threadIdx.x, wid = tid >> 5, lane = tid & 31;
    sbias[tid] = bias[(long)e * N + n0 + tid];

    const int rA = tid >> 2, cq = tid & 3;
    const __half* ap[4];
    const __half* bp[4];
#pragma unroll
    for (int j = 0; j < 4; j++) {
        long r = arow0 + rA + 32 * j;
        if (r > S_ - 1) r = S_ - 1;
        ap[j] = A + r * (long)K + cq * 8;
        bp[j] = Bw + ((long)e * N + n0 + rA + 32 * j) * (long)K + cq * 8;
    }
    const uint32_t sA = sb + rA * 80 + cq * 16;
    const uint32_t sB = sb + A_B + rA * 80 + cq * 16;

#define LOAD_STAGE(soff, koff) do {                                    \
    _Pragma("unroll")                                                  \
    for (int j = 0; j < 4; j++) {                                      \
        cp16(sA + (soff) + j * 32 * 80, ap[j] + (koff));               \
        cp16(sB + (soff) + j * 32 * 80, bp[j] + (koff));               \
    }                                                                  \
} while (0)

    LOAD_STAGE(0, 0);          CP_COMMIT();
    LOAD_STAGE(ST_B, 32);      CP_COMMIT();
    LOAD_STAGE(2 * ST_B, 64);  CP_COMMIT();

    const int base_m = (wid & 1) * 64;
    const int base_n = (wid >> 1) * 64;
    const uint32_t arow = base_m + (lane & 15);
    const uint32_t acol = (lane >> 4) << 3;
    const uint32_t brow = base_n + ((lane >> 4) << 3) + (lane & 7);
    const uint32_t bcol = ((lane >> 3) & 1) << 3;

    float acc[4][8][4];
#pragma unroll
    for (int mi = 0; mi < 4; mi++)
#pragma unroll
        for (int nj = 0; nj < 8; nj++)
#pragma unroll
            for (int q = 0; q < 4; q++) acc[mi][nj][q] = 0.f;

    const int NIT = K / 32;
#pragma unroll 1
    for (int it = 0; it < NIT; it++) {
        CP_WAIT2();
        __syncthreads();
        const uint32_t st = sb + (it & (NST - 1)) * ST_B;
#pragma unroll
        for (int ks = 0; ks < 2; ks++) {
            uint32_t a[4][4], b[4][4];
            uint32_t ab = st + (arow * 40 + ks * 16 + acol) * 2;
            uint32_t bb = st + A_B + (brow * 40 + ks * 16 + bcol) * 2;
#pragma unroll
            for (int mi = 0; mi < 4; mi++) ldsm4(a[mi], ab + mi * 1280);
#pragma unroll
            for (int ni = 0; ni < 4; ni++) ldsm4(b[ni], bb + ni * 1280);
#pragma unroll
            for (int mi = 0; mi < 4; mi++)
#pragma unroll
                for (int ni = 0; ni < 4; ni++)
#pragma unroll
                    for (int h = 0; h < 2; h++)
                        mma16816(acc[mi][ni * 2 + h], a[mi], &b[ni][h * 2]);
        }
        if (it + 3 < NIT) {
            const uint32_t so = ((it + 3) & (NST - 1)) * ST_B;
            LOAD_STAGE(so, (it + 3) * 32);
        }
        CP_COMMIT();
    }
#undef LOAD_STAGE

#pragma unroll
    for (int mi = 0; mi < 4; mi++) {
        int gr0 = m0 + base_m + mi * 16 + (lane >> 2);
        bool v0 = gr0 < cnt, v1 = (gr0 + 8) < cnt;
        long s0 = (long)(off + gr0), s1 = s0 + 8;
#pragma unroll
        for (int nj = 0; nj < 8; nj++) {
            int col = base_n + nj * 8 + (lane & 3) * 2;
            float2 bv = *(float2*)&sbias[col];
            float x0 = acc[mi][nj][0] + bv.x;
            float x1 = acc[mi][nj][1] + bv.y;
            float x2 = acc[mi][nj][2] + bv.x;
            float x3 = acc[mi][nj][3] + bv.y;
            if (RELU) {
                x0 = fmaxf(x0, 0.f); x1 = fmaxf(x1, 0.f);
                x2 = fmaxf(x2, 0.f); x3 = fmaxf(x3, 0.f);
            }
            long gcol = n0 + col;
            if (HALF_OUT) {
                if (v0) {
                    __half2 hp; hp.x = __float2half_rn(x0); hp.y = __float2half_rn(x1);
                    *(__half2*)(oh + s0 * N + gcol) = hp;
                }
                if (v1) {
                    __half2 hp; hp.x = __float2half_rn(x2); hp.y = __float2half_rn(x3);
                    *(__half2*)(oh + s1 * N + gcol) = hp;
                }
            } else {
                if (v0) { float2 v; v.x = x0; v.y = x1; *(float2*)(of + s0 * N + gcol) = v; }
                if (v1) { float2 v; v.x = x2; v.y = x3; *(float2*)(of + s1 * N + gcol) = v; }
            }
        }
    }
}

// ---------------- combine ----------------
__global__ void k_combine(float* __restrict__ out) {
    int idx = blockIdx.x * 256 + threadIdx.x;
    int b = idx >> 8;
    int o4 = idx & 255;
    float w0 = g_wt[2 * b], w1 = g_wt[2 * b + 1];
    const float4* r0 = (const float4*)(g_eo + (long)g_slot[2 * b] * O_);
    const float4* r1 = (const float4*)(g_eo + (long)g_slot[2 * b + 1] * O_);
    float4 a = r0[o4], c = r1[o4], v;
    v.x = w0 * a.x + w1 * c.x;
    v.y = w0 * a.y + w1 * c.y;
    v.z = w0 * a.z + w1 * c.z;
    v.w = w0 * a.w + w1 * c.w;
    ((float4*)out)[idx] = v;
}

// ---------------- host ----------------
#define SMEM_DYN (NST * ST_B)

extern "C" void kernel_launch(void* const* d_in, const int* in_sizes, int n_in,
                              void* d_out, int out_size) {
    XPtrs xs;
    for (int i = 0; i < E_; i++) xs.p[i] = (const float*)d_in[i];
    const float* gw    = (const float*)d_in[8];
    const float* gb    = (const float*)d_in[9];
    const float* w_in  = (const float*)d_in[10];
    const float* b_in  = (const float*)d_in[11];
    const float* w_h   = (const float*)d_in[12];
    const float* b_h   = (const float*)d_in[13];
    const float* w_out = (const float*)d_in[14];
    const float* b_out = (const float*)d_in[15];
    float* out = (float*)d_out;

    void *xg, *h1, *h2, *win, *wh, *wo, *eo;
    cudaGetSymbolAddress(&xg, g_xg);
    cudaGetSymbolAddress(&h1, g_h1);
    cudaGetSymbolAddress(&h2, g_h2);
    cudaGetSymbolAddress(&win, g_win);
    cudaGetSymbolAddress(&wh, g_wh);
    cudaGetSymbolAddress(&wo, g_wo);
    cudaGetSymbolAddress(&eo, g_eo);

    cudaFuncSetAttribute((const void*)k_mma<1024, 2048, true, true>,
                         cudaFuncAttributeMaxDynamicSharedMemorySize, SMEM_DYN);
    cudaFuncSetAttribute((const void*)k_mma<2048, 2048, true, true>,
                         cudaFuncAttributeMaxDynamicSharedMemorySize, SMEM_DYN);
    cudaFuncSetAttribute((const void*)k_mma<2048, 1024, false, false>,
                         cudaFuncAttributeMaxDynamicSharedMemorySize, SMEM_DYN);

    // ---- side stream for weight conversion (fork/join via events; capture-safe).
    // Created per call and intentionally NOT destroyed here: destroying a stream
    // that participates in an active capture invalidates the capture. These are
    // host-side objects only (no device memory), and kernel_launch is invoked a
    // handful of times per run.
    cudaStream_t s2 = 0;
    cudaEvent_t evF = 0, ev1 = 0, ev2 = 0, ev3 = 0;
    bool ok = cudaStreamCreateWithFlags(&s2, cudaStreamNonBlocking) == cudaSuccess;
    if (ok) ok = cudaEventCreateWithFlags(&evF, cudaEventDisableTiming) == cudaSuccess;
    if (ok) ok = cudaEventCreateWithFlags(&ev1, cudaEventDisableTiming) == cudaSuccess;
    if (ok) ok = cudaEventCreateWithFlags(&ev2, cudaEventDisableTiming) == cudaSuccess;
    if (ok) ok = cudaEventCreateWithFlags(&ev3, cudaEventDisableTiming) == cudaSuccess;

    if (ok) {
        // fork side stream from the main (capture-origin) stream
        cudaEventRecord(evF, 0);
        cudaStreamWaitEvent(s2, evF, 0);
        k_convw<<<dim3(H_ / 32, D_ / 32, E_), dim3(32, 8), 0, s2>>>(w_in, (__half*)win, D_, H_);
        cudaEventRecord(ev1, s2);
        k_convw<<<dim3(H_ / 32, H_ / 32, E_), dim3(32, 8), 0, s2>>>(w_h, (__half*)wh, H_, H_);
        cudaEventRecord(ev2, s2);
        k_convw<<<dim3(O_ / 32, H_ / 32, E_), dim3(32, 8), 0, s2>>>(w_out, (__half*)wo, H_, O_);
        cudaEventRecord(ev3, s2);
    } else {
        k_convw<<<dim3(H_ / 32, D_ / 32, E_), dim3(32, 8)>>>(w_in, (__half*)win, D_, H_);
        k_convw<<<dim3(H_ / 32, H_ / 32, E_), dim3(32, 8)>>>(w_h, (__half*)wh, H_, H_);
        k_convw<<<dim3(O_ / 32, H_ / 32, E_), dim3(32, 8)>>>(w_out, (__half*)wo, H_, O_);
    }

    k_zero<<<1, 32>>>();
    k_gate<<<B_ / 4, 256>>>(xs, gw, gb);
    k_scan<<<1, 32>>>();
    k_fill<<<S_ / 256, 256>>>();
    k_gather<<<S_, 128>>>(xs);

    if (ok) cudaStreamWaitEvent(0, ev1, 0);
    k_mma<1024, 2048, true, true><<<dim3(H_ / 128, S_ / 128, E_), 128, SMEM_DYN>>>(
        (const __half*)xg, (const __half*)win, b_in, (__half*)h1, nullptr);
    if (ok) cudaStreamWaitEvent(0, ev2, 0);
    k_mma<2048, 2048, true, true><<<dim3(H_ / 128, S_ / 128, E_), 128, SMEM_DYN>>>(
        (const __half*)h1, (const __half*)wh, b_h, (__half*)h2, nullptr);
    if (ok) cudaStreamWaitEvent(0, ev3, 0);
    k_mma<2048, 1024, false, false><<<dim3(O_ / 128, S_ / 128, E_), 128, SMEM_DYN>>>(
        (const __half*)h2, (const __half*)wo, b_out, nullptr, (float*)eo);

    k_combine<<<(B_ * O_ / 4) / 256, 256>>>(out);
}